// round 11
// baseline (speedup 1.0000x reference)
#include <cuda_runtime.h>
#include <cuda_fp16.h>
#include <cstdint>
#include <math.h>

#define NTOK 8192
#define DDIM 2048
#define HDIM 8192
#define ODIM 2048
#define NEXP 8
#define MAXSLOTS (NTOK * 2)
#define SLOTPAD (MAXSLOTS + 256)

// ---------------- device scratch (static: no allocations allowed) ----------------
// Single shared fp16 weight buffer, reused W1 -> GEMM1 -> W2 -> GEMM2.
__device__ __align__(16) __half g_wbuf[(size_t)NEXP * HDIM * DDIM]; // 268 MB
__device__ __align__(16) __half g_xa[(size_t)SLOTPAD * DDIM];       // gathered x, fp16
__device__ __align__(16) __half g_h [(size_t)SLOTPAD * HDIM];       // hidden acts, fp16
__device__ int    g_slot_token[MAXSLOTS];
__device__ float  g_slot_w[MAXSLOTS];
__device__ int    g_tok_e[NTOK * 2];
__device__ float  g_tok_w[NTOK * 2];
__device__ int    g_counts[NEXP];
__device__ int    g_offsets[NEXP + 1];
__device__ float  g_sumP[NEXP];

// ---------------- fused zero + init ----------------
__global__ void zero_init_kernel(float* out, long long n) {
    long long i = (long long)blockIdx.x * blockDim.x + threadIdx.x;
    long long stride = (long long)gridDim.x * blockDim.x;
    for (; i < n; i += stride) out[i] = 0.f;
    if (blockIdx.x == 0 && threadIdx.x < NEXP) {
        g_counts[threadIdx.x] = 0;
        g_sumP[threadIdx.x] = 0.f;
    }
}

// ---------------- router (validated R3/R7) ----------------
__global__ void router_kernel(const float* __restrict__ x,
                              const float* __restrict__ gW,
                              const float* __restrict__ gb) {
    __shared__ float sP[NEXP];
    int tid = threadIdx.x, lane = tid & 31, warp = tid >> 5;
    if (tid < NEXP) sP[tid] = 0.f;
    __syncthreads();

    int n = blockIdx.x * 8 + warp;
    float acc[NEXP];
#pragma unroll
    for (int e = 0; e < NEXP; e++) acc[e] = 0.f;
    const float* xr = x + (size_t)n * DDIM;
    for (int d = lane; d < DDIM; d += 32) {
        float xv = xr[d];
        const float4* g = reinterpret_cast<const float4*>(gW + (size_t)d * NEXP);
        float4 g0 = g[0], g1 = g[1];
        acc[0] += xv * g0.x; acc[1] += xv * g0.y; acc[2] += xv * g0.z; acc[3] += xv * g0.w;
        acc[4] += xv * g1.x; acc[5] += xv * g1.y; acc[6] += xv * g1.z; acc[7] += xv * g1.w;
    }
#pragma unroll
    for (int e = 0; e < NEXP; e++) {
        float v = acc[e];
#pragma unroll
        for (int o = 16; o > 0; o >>= 1) v += __shfl_xor_sync(0xffffffffu, v, o);
        acc[e] = v;
    }
    if (lane == 0) {
        float p[NEXP];
        float m = -1e30f;
#pragma unroll
        for (int e = 0; e < NEXP; e++) { p[e] = acc[e] + gb[e]; m = fmaxf(m, p[e]); }
        float s = 0.f;
#pragma unroll
        for (int e = 0; e < NEXP; e++) { p[e] = expf(p[e] - m); s += p[e]; }
        float inv = 1.f / s;
#pragma unroll
        for (int e = 0; e < NEXP; e++) { p[e] *= inv; atomicAdd(&sP[e], p[e]); }
        int i0 = 0;
#pragma unroll
        for (int e = 1; e < NEXP; e++) if (p[e] > p[i0]) i0 = e;
        int i1 = (i0 == 0) ? 1 : 0;
#pragma unroll
        for (int e = 0; e < NEXP; e++) if (e != i0 && p[e] > p[i1]) i1 = e;
        float g0 = p[i0], g1 = p[i1], winv = 1.f / (g0 + g1);
        g_tok_e[2 * n] = i0;  g_tok_e[2 * n + 1] = i1;
        g_tok_w[2 * n] = g0 * winv;  g_tok_w[2 * n + 1] = g1 * winv;
        atomicAdd(&g_counts[i0], 1); atomicAdd(&g_counts[i1], 1);
    }
    __syncthreads();
    if (tid < NEXP) atomicAdd(&g_sumP[tid], sP[tid]);
}

// ---------------- assign + setup fused: one block per expert ----------------
// Each block derives its own offset from g_counts (post-router). Block 0 also
// writes g_offsets[] for the GEMMs and lb_loss to out[lbIdx].
__global__ void assign_kernel(float* __restrict__ out, long long lbIdx) {
    const int e = blockIdx.x;
    const int tid = threadIdx.x;
    __shared__ int svals[256];
    __shared__ int sbase;
    if (tid == 0) {
        int off = 0;
#pragma unroll
        for (int i = 0; i < NEXP; i++) {
            if (i == e) break;
            off += g_counts[i];
        }
        // recompute without break-dependent unroll weirdness
        off = 0;
        for (int i = 0; i < e; i++) off += g_counts[i];
        sbase = off;
        g_offsets[e] = off;
        if (e == 0) {
            int tot = 0;
#pragma unroll
            for (int i = 0; i < NEXP; i++) tot += g_counts[i];
            g_offsets[NEXP] = tot;
            float lb = 0.f;
#pragma unroll
            for (int i = 0; i < NEXP; i++) {
                float P = g_sumP[i] / (float)NTOK;
                lb += P * P;
            }
            out[lbIdx] = lb * (float)NEXP;
        }
    }
    __syncthreads();
    for (int t0 = 0; t0 < NTOK; t0 += 256) {
        int n = t0 + tid;
        int sel = 0; float w = 0.f;
        int e0 = g_tok_e[2 * n], e1 = g_tok_e[2 * n + 1];
        if (e0 == e)      { sel = 1; w = g_tok_w[2 * n]; }
        else if (e1 == e) { sel = 1; w = g_tok_w[2 * n + 1]; }
        svals[tid] = sel;
        __syncthreads();
#pragma unroll
        for (int o = 1; o < 256; o <<= 1) {
            int t = (tid >= o) ? svals[tid - o] : 0;
            __syncthreads();
            svals[tid] += t;
            __syncthreads();
        }
        if (sel) {
            int pos = sbase + svals[tid] - 1;
            g_slot_token[pos] = n;
            g_slot_w[pos] = w;
        }
        int total = svals[255];
        __syncthreads();
        if (tid == 0) sbase += total;
        __syncthreads();
    }
}

// ---------------- preconvert kernels ----------------
__global__ void convert_w_kernel(const float* __restrict__ src, __half* __restrict__ dst,
                                 size_t n8) {
    size_t i = (size_t)blockIdx.x * blockDim.x + threadIdx.x;
    size_t stride = (size_t)gridDim.x * blockDim.x;
    for (; i < n8; i += stride) {
        const float4* s = reinterpret_cast<const float4*>(src + i * 8);
        float4 v0 = s[0], v1 = s[1];
        __half2 h0 = __floats2half2_rn(v0.x, v0.y);
        __half2 h1 = __floats2half2_rn(v0.z, v0.w);
        __half2 h2 = __floats2half2_rn(v1.x, v1.y);
        __half2 h3 = __floats2half2_rn(v1.z, v1.w);
        uint2* d = reinterpret_cast<uint2*>(dst + i * 8);
        d[0] = make_uint2(*(uint32_t*)&h0, *(uint32_t*)&h1);
        d[1] = make_uint2(*(uint32_t*)&h2, *(uint32_t*)&h3);
    }
}

__global__ void gather_x_kernel(const float* __restrict__ x) {
    int slot = blockIdx.x;
    int token = g_slot_token[slot];
    const float* src = x + (size_t)token * DDIM;
    __half* dst = g_xa + (size_t)slot * DDIM;
    int t = threadIdx.x;
#pragma unroll
    for (int i = 0; i < 2; i++) {
        int c = (t + i * 256) * 4;
        float4 v = *reinterpret_cast<const float4*>(src + c);
        __half2 h0 = __floats2half2_rn(v.x, v.y);
        __half2 h1 = __floats2half2_rn(v.z, v.w);
        *reinterpret_cast<uint2*>(dst + c) = make_uint2(*(uint32_t*)&h0, *(uint32_t*)&h1);
    }
}

// ---------------- HMMA GEMM: BM=256 BN=128 BK=32, 512 thr, 6-stage cp.async ----------------
#define BM 256
#define BN 128
#define BK 32
#define STAGES 6
#define STRIDE 40                       // halves; 80B rows -> conflict-free ldsm
#define A_STG (BM * STRIDE * 2)         // 20480 B
#define B_STG (BN * STRIDE * 2)         // 10240 B
#define GEMM_SMEM (STAGES * (A_STG + B_STG))  // 184320 B

__device__ __forceinline__ uint32_t smem_u32(const void* p) {
    uint32_t a;
    asm("{ .reg .u64 t; cvta.to.shared.u64 t, %1; cvt.u32.u64 %0, t; }" : "=r"(a) : "l"(p));
    return a;
}
__device__ __forceinline__ void cpa16(uint32_t dst, const void* src) {
    asm volatile("cp.async.cg.shared.global [%0], [%1], 16;" :: "r"(dst), "l"(src));
}
__device__ __forceinline__ void cpa_commit() {
    asm volatile("cp.async.commit_group;" ::: "memory");
}
__device__ __forceinline__ void cpa_wait4() {
    asm volatile("cp.async.wait_group 4;" ::: "memory");
}
__device__ __forceinline__ void ldsm4(uint32_t& r0, uint32_t& r1, uint32_t& r2, uint32_t& r3,
                                      uint32_t addr) {
    asm volatile("ldmatrix.sync.aligned.m8n8.x4.shared.b16 {%0,%1,%2,%3}, [%4];\n"
                 : "=r"(r0), "=r"(r1), "=r"(r2), "=r"(r3) : "r"(addr));
}
__device__ __forceinline__ void mma16816(float* d, const uint32_t* a, const uint32_t* b) {
    asm volatile(
        "mma.sync.aligned.m16n8k16.row.col.f32.f16.f16.f32 "
        "{%0,%1,%2,%3},{%4,%5,%6,%7},{%8,%9},{%0,%1,%2,%3};\n"
        : "+f"(d[0]), "+f"(d[1]), "+f"(d[2]), "+f"(d[3])
        : "r"(a[0]), "r"(a[1]), "r"(a[2]), "r"(a[3]), "r"(b[0]), "r"(b[1]));
}

// MODE 0: h = relu(A @ W1[e]^T + b1) -> g_h (fp16)
// MODE 1: out[token] += w * (A @ W2[e]^T + b2)   (atomicAdd; 2 adds/element total)
template <int MODE>
__global__ void __launch_bounds__(512, 1) ffn_gemm(const __half* __restrict__ Abase,
                                                   const __half* __restrict__ Wbase,
                                                   const float* __restrict__ bbase,
                                                   float* __restrict__ out) {
    constexpr int KDIM = (MODE == 0) ? DDIM : HDIM;
    constexpr int NDIM = (MODE == 0) ? HDIM : ODIM;
    constexpr int KT = KDIM / BK;

    const int e = blockIdx.z;
    const int cnt = g_counts[e];
    const int mtile = blockIdx.y;
    if (mtile * BM >= cnt) return;
    const int ntile = blockIdx.x;
    const int off = g_offsets[e];

    extern __shared__ __align__(16) char smem[];
    const uint32_t sa = smem_u32(smem);            // A stages at sa + s*A_STG
    const uint32_t sbB = sa + STAGES * A_STG;      // B stages

    const int tid = threadIdx.x;
    const int lane = tid & 31;
    const int warp = tid >> 5;
    const int wm = warp & 3;   // 4 warp-rows x 64
    const int wn = warp >> 2;  // 4 warp-cols x 32

    const __half* Aexp = Abase + (size_t)(off + mtile * BM) * KDIM;
    const __half* Wexp = Wbase + (size_t)e * NDIM * KDIM + (size_t)(ntile * BN) * KDIM;

    // copy maps: 16B chunks. A: 256 rows x 4 = 1024 chunks; B: 128 x 4 = 512 chunks.
    const int arow0 = tid >> 2, ac8 = tid & 3;     // A chunk tid; chunk tid+512
    const int arow1 = (tid + 512) >> 2;
    const int brow = tid >> 2;

    auto copy_stage = [&](int kt, int s) {
        const int ko = kt * BK + ac8 * 8;
        cpa16(sa + s * A_STG + arow0 * 80 + ac8 * 16, Aexp + (size_t)arow0 * KDIM + ko);
        cpa16(sa + s * A_STG + arow1 * 80 + ac8 * 16, Aexp + (size_t)arow1 * KDIM + ko);
        cpa16(sbB + s * B_STG + brow * 80 + ac8 * 16, Wexp + (size_t)brow * KDIM + ko);
    };

    float acc[4][4][4];
#pragma unroll
    for (int mi = 0; mi < 4; mi++)
#pragma unroll
        for (int ni = 0; ni < 4; ni++)
#pragma unroll
            for (int j = 0; j < 4; j++) acc[mi][ni][j] = 0.f;

    // prologue: fill STAGES-1 = 5 stages
#pragma unroll
    for (int i = 0; i < STAGES - 1; i++) {
        if (i < KT) copy_stage(i, i);
        cpa_commit();
    }

    const uint32_t aFragBase = sa + (wm * 64 + (lane & 15)) * 80 + ((lane >> 4) << 3) * 2;
    const uint32_t bFragBase =
        sbB + (wn * 32 + ((lane >> 4) << 3) + (lane & 7)) * 80 + (((lane >> 3) & 1) << 3) * 2;

    int buf = 0;
    for (int kt = 0; kt < KT; kt++) {
        cpa_wait4();
        __syncthreads();   // publishes stage `buf`; proves stage being refilled was consumed
        {
            int nk = kt + STAGES - 1;
            if (nk < KT) {
                int ns = nk - STAGES * (nk / STAGES);  // nk % STAGES
                copy_stage(nk, ns);
            }
            cpa_commit();
        }
#pragma unroll
        for (int kk = 0; kk < 2; kk++) {
            uint32_t af[4][4], bf[4][2];
#pragma unroll
            for (int mi = 0; mi < 4; mi++)
                ldsm4(af[mi][0], af[mi][1], af[mi][2], af[mi][3],
                      aFragBase + buf * A_STG + mi * 16 * 80 + kk * 32);
#pragma unroll
            for (int pr = 0; pr < 2; pr++)
                ldsm4(bf[pr * 2][0], bf[pr * 2][1], bf[pr * 2 + 1][0], bf[pr * 2 + 1][1],
                      bFragBase + buf * B_STG + pr * 16 * 80 + kk * 32);
#pragma unroll
            for (int mi = 0; mi < 4; mi++)
#pragma unroll
                for (int ni = 0; ni < 4; ni++) mma16816(acc[mi][ni], af[mi], bf[ni]);
        }
        buf++;
        if (buf == STAGES) buf = 0;
    }

    // ---- epilogue ----
    const int lrow = lane >> 2;
    const int lcol = (lane & 3) * 2;
#pragma unroll
    for (int mi = 0; mi < 4; mi++) {
#pragma unroll
        for (int hh = 0; hh < 2; hh++) {
            int rloc = wm * 64 + mi * 16 + lrow + hh * 8;
            int gm = mtile * BM + rloc;
            if (gm < cnt) {
                if constexpr (MODE == 0) {
                    __half* hrow = g_h + (size_t)(off + gm) * HDIM;
#pragma unroll
                    for (int ni = 0; ni < 4; ni++) {
                        int col = ntile * BN + wn * 32 + ni * 8 + lcol;
                        float c0 = acc[mi][ni][hh * 2 + 0] + __ldg(&bbase[e * NDIM + col]);
                        float c1 = acc[mi][ni][hh * 2 + 1] + __ldg(&bbase[e * NDIM + col + 1]);
                        __half2 hv = __floats2half2_rn(fmaxf(c0, 0.f), fmaxf(c1, 0.f));
                        *reinterpret_cast<__half2*>(hrow + col) = hv;
                    }
                } else {
                    float w = g_slot_w[off + gm];
                    float* orow = out + (size_t)g_slot_token[off + gm] * ODIM;
#pragma unroll
                    for (int ni = 0; ni < 4; ni++) {
                        int col = ntile * BN + wn * 32 + ni * 8 + lcol;
                        float c0 = acc[mi][ni][hh * 2 + 0] + __ldg(&bbase[e * NDIM + col]);
                        float c1 = acc[mi][ni][hh * 2 + 1] + __ldg(&bbase[e * NDIM + col + 1]);
                        atomicAdd(&orow[col], w * c0);
                        atomicAdd(&orow[col + 1], w * c1);
                    }
                }
            }
        }
    }
}

// ---------------- launch ----------------
extern "C" void kernel_launch(void* const* d_in, const int* in_sizes, int n_in,
                              void* d_out, int out_size) {
    const float* x  = (const float*)d_in[0];
    const float* gW = (const float*)d_in[1];
    const float* gb = (const float*)d_in[2];
    const float* W1 = (const float*)d_in[3];
    const float* b1 = (const float*)d_in[4];
    const float* W2 = (const float*)d_in[5];
    const float* b2 = (const float*)d_in[6];
    float* out = (float*)d_out;

    // Unconditional every call (no static guards — harness determinism rule).
    cudaFuncSetAttribute(ffn_gemm<0>, cudaFuncAttributeMaxDynamicSharedMemorySize, GEMM_SMEM);
    cudaFuncSetAttribute(ffn_gemm<1>, cudaFuncAttributeMaxDynamicSharedMemorySize, GEMM_SMEM);

    __half* wbuf = nullptr; __half* xad = nullptr; __half* hd = nullptr;
    cudaGetSymbolAddress((void**)&wbuf, g_wbuf);
    cudaGetSymbolAddress((void**)&xad, g_xa);
    cudaGetSymbolAddress((void**)&hd, g_h);
    size_t n8w = (size_t)NEXP * HDIM * DDIM / 8;

    zero_init_kernel<<<2048, 256>>>(out, (long long)out_size);         // 1
    router_kernel<<<NTOK / 8, 256>>>(x, gW, gb);                       // 2
    assign_kernel<<<NEXP, 256>>>(out, (long long)out_size - 1);        // 3
    gather_x_kernel<<<MAXSLOTS, 256>>>(x);                             // 4
    convert_w_kernel<<<4096, 256>>>(W1, wbuf, n8w);                    // 5
    ffn_gemm<0><<<dim3(HDIM / BN, MAXSLOTS / BM, NEXP), 512, GEMM_SMEM>>>(xad, wbuf, b1,
                                                                          nullptr);  // 6
    convert_w_kernel<<<4096, 256>>>(W2, wbuf, n8w);                    // 7
    ffn_gemm<1><<<dim3(ODIM / BN, MAXSLOTS / BM, NEXP), 512, GEMM_SMEM>>>(hd, wbuf, b2, out); // 8
}

// round 12
// speedup vs baseline: 1.2318x; 1.2318x over previous
#include <cuda_runtime.h>
#include <cuda_fp16.h>
#include <cstdint>
#include <math.h>

#define NTOK 8192
#define DDIM 2048
#define HDIM 8192
#define ODIM 2048
#define NEXP 8
#define MAXSLOTS (NTOK * 2)
#define SLOTPAD (MAXSLOTS + 256)

// ---------------- device scratch (static: no allocations allowed) ----------------
__device__ __align__(16) __half g_wbuf[(size_t)NEXP * HDIM * DDIM]; // 268 MB (reused W1->W2)
__device__ __align__(16) __half g_xa[(size_t)SLOTPAD * DDIM];       // gathered x, fp16
__device__ __align__(16) __half g_h [(size_t)SLOTPAD * HDIM];       // hidden acts, fp16
__device__ int    g_slot_token[MAXSLOTS];
__device__ float  g_slot_w[MAXSLOTS];
__device__ int    g_tok_e[NTOK * 2];
__device__ float  g_tok_w[NTOK * 2];
__device__ int    g_counts[NEXP];
__device__ int    g_offsets[NEXP + 1];
__device__ float  g_sumP[NEXP];

// ---------------- fused zero + init ----------------
__global__ void zero_init_kernel(float* out, long long n) {
    long long i = (long long)blockIdx.x * blockDim.x + threadIdx.x;
    long long stride = (long long)gridDim.x * blockDim.x;
    for (; i < n; i += stride) out[i] = 0.f;
    if (blockIdx.x == 0 && threadIdx.x < NEXP) {
        g_counts[threadIdx.x] = 0;
        g_sumP[threadIdx.x] = 0.f;
    }
}

// ---------------- router (validated R3/R7) ----------------
__global__ void router_kernel(const float* __restrict__ x,
                              const float* __restrict__ gW,
                              const float* __restrict__ gb) {
    __shared__ float sP[NEXP];
    int tid = threadIdx.x, lane = tid & 31, warp = tid >> 5;
    if (tid < NEXP) sP[tid] = 0.f;
    __syncthreads();

    int n = blockIdx.x * 8 + warp;
    float acc[NEXP];
#pragma unroll
    for (int e = 0; e < NEXP; e++) acc[e] = 0.f;
    const float* xr = x + (size_t)n * DDIM;
    for (int d = lane; d < DDIM; d += 32) {
        float xv = xr[d];
        const float4* g = reinterpret_cast<const float4*>(gW + (size_t)d * NEXP);
        float4 g0 = g[0], g1 = g[1];
        acc[0] += xv * g0.x; acc[1] += xv * g0.y; acc[2] += xv * g0.z; acc[3] += xv * g0.w;
        acc[4] += xv * g1.x; acc[5] += xv * g1.y; acc[6] += xv * g1.z; acc[7] += xv * g1.w;
    }
#pragma unroll
    for (int e = 0; e < NEXP; e++) {
        float v = acc[e];
#pragma unroll
        for (int o = 16; o > 0; o >>= 1) v += __shfl_xor_sync(0xffffffffu, v, o);
        acc[e] = v;
    }
    if (lane == 0) {
        float p[NEXP];
        float m = -1e30f;
#pragma unroll
        for (int e = 0; e < NEXP; e++) { p[e] = acc[e] + gb[e]; m = fmaxf(m, p[e]); }
        float s = 0.f;
#pragma unroll
        for (int e = 0; e < NEXP; e++) { p[e] = expf(p[e] - m); s += p[e]; }
        float inv = 1.f / s;
#pragma unroll
        for (int e = 0; e < NEXP; e++) { p[e] *= inv; atomicAdd(&sP[e], p[e]); }
        int i0 = 0;
#pragma unroll
        for (int e = 1; e < NEXP; e++) if (p[e] > p[i0]) i0 = e;
        int i1 = (i0 == 0) ? 1 : 0;
#pragma unroll
        for (int e = 0; e < NEXP; e++) if (e != i0 && p[e] > p[i1]) i1 = e;
        float g0 = p[i0], g1 = p[i1], winv = 1.f / (g0 + g1);
        g_tok_e[2 * n] = i0;  g_tok_e[2 * n + 1] = i1;
        g_tok_w[2 * n] = g0 * winv;  g_tok_w[2 * n + 1] = g1 * winv;
        atomicAdd(&g_counts[i0], 1); atomicAdd(&g_counts[i1], 1);
    }
    __syncthreads();
    if (tid < NEXP) atomicAdd(&g_sumP[tid], sP[tid]);
}

// ---------------- assign + setup fused (validated R11 for correctness) ----------------
__global__ void assign_kernel(float* __restrict__ out, long long lbIdx) {
    const int e = blockIdx.x;
    const int tid = threadIdx.x;
    __shared__ int svals[256];
    __shared__ int sbase;
    if (tid == 0) {
        int off = 0;
        for (int i = 0; i < e; i++) off += g_counts[i];
        sbase = off;
        g_offsets[e] = off;
        if (e == 0) {
            int tot = 0;
#pragma unroll
            for (int i = 0; i < NEXP; i++) tot += g_counts[i];
            g_offsets[NEXP] = tot;
            float lb = 0.f;
#pragma unroll
            for (int i = 0; i < NEXP; i++) {
                float P = g_sumP[i] / (float)NTOK;
                lb += P * P;
            }
            out[lbIdx] = lb * (float)NEXP;
        }
    }
    __syncthreads();
    for (int t0 = 0; t0 < NTOK; t0 += 256) {
        int n = t0 + tid;
        int sel = 0; float w = 0.f;
        int e0 = g_tok_e[2 * n], e1 = g_tok_e[2 * n + 1];
        if (e0 == e)      { sel = 1; w = g_tok_w[2 * n]; }
        else if (e1 == e) { sel = 1; w = g_tok_w[2 * n + 1]; }
        svals[tid] = sel;
        __syncthreads();
#pragma unroll
        for (int o = 1; o < 256; o <<= 1) {
            int t = (tid >= o) ? svals[tid - o] : 0;
            __syncthreads();
            svals[tid] += t;
            __syncthreads();
        }
        if (sel) {
            int pos = sbase + svals[tid] - 1;
            g_slot_token[pos] = n;
            g_slot_w[pos] = w;
        }
        int total = svals[255];
        __syncthreads();
        if (tid == 0) sbase += total;
        __syncthreads();
    }
}

// ---------------- preconvert kernels ----------------
__global__ void convert_w_kernel(const float* __restrict__ src, __half* __restrict__ dst,
                                 size_t n8) {
    size_t i = (size_t)blockIdx.x * blockDim.x + threadIdx.x;
    size_t stride = (size_t)gridDim.x * blockDim.x;
    for (; i < n8; i += stride) {
        const float4* s = reinterpret_cast<const float4*>(src + i * 8);
        float4 v0 = s[0], v1 = s[1];
        __half2 h0 = __floats2half2_rn(v0.x, v0.y);
        __half2 h1 = __floats2half2_rn(v0.z, v0.w);
        __half2 h2 = __floats2half2_rn(v1.x, v1.y);
        __half2 h3 = __floats2half2_rn(v1.z, v1.w);
        uint2* d = reinterpret_cast<uint2*>(dst + i * 8);
        d[0] = make_uint2(*(uint32_t*)&h0, *(uint32_t*)&h1);
        d[1] = make_uint2(*(uint32_t*)&h2, *(uint32_t*)&h3);
    }
}

__global__ void gather_x_kernel(const float* __restrict__ x) {
    int slot = blockIdx.x;
    int token = g_slot_token[slot];
    const float* src = x + (size_t)token * DDIM;
    __half* dst = g_xa + (size_t)slot * DDIM;
    int t = threadIdx.x;
#pragma unroll
    for (int i = 0; i < 2; i++) {
        int c = (t + i * 256) * 4;
        float4 v = *reinterpret_cast<const float4*>(src + c);
        __half2 h0 = __floats2half2_rn(v.x, v.y);
        __half2 h1 = __floats2half2_rn(v.z, v.w);
        *reinterpret_cast<uint2*>(dst + c) = make_uint2(*(uint32_t*)&h0, *(uint32_t*)&h1);
    }
}

// ------- HMMA GEMM: BM=256 BN=128 BK=64 (SW128 128B rows), 512 thr, 4-stage cp.async -------
#define BM 256
#define BN 128
#define BK 64
#define STAGES 4
#define A_STG (BM * 128)                       // 32768 B (256 rows x 128B)
#define B_STG (BN * 128)                       // 16384 B
#define GEMM_SMEM (STAGES * (A_STG + B_STG))   // 196608 B

__device__ __forceinline__ uint32_t smem_u32(const void* p) {
    uint32_t a;
    asm("{ .reg .u64 t; cvta.to.shared.u64 t, %1; cvt.u32.u64 %0, t; }" : "=r"(a) : "l"(p));
    return a;
}
__device__ __forceinline__ void cpa16(uint32_t dst, const void* src) {
    asm volatile("cp.async.cg.shared.global [%0], [%1], 16;" :: "r"(dst), "l"(src));
}
__device__ __forceinline__ void cpa_commit() {
    asm volatile("cp.async.commit_group;" ::: "memory");
}
__device__ __forceinline__ void cpa_wait2() {
    asm volatile("cp.async.wait_group 2;" ::: "memory");
}
__device__ __forceinline__ void ldsm4(uint32_t& r0, uint32_t& r1, uint32_t& r2, uint32_t& r3,
                                      uint32_t addr) {
    asm volatile("ldmatrix.sync.aligned.m8n8.x4.shared.b16 {%0,%1,%2,%3}, [%4];\n"
                 : "=r"(r0), "=r"(r1), "=r"(r2), "=r"(r3) : "r"(addr));
}
__device__ __forceinline__ void mma16816(float* d, const uint32_t* a, const uint32_t* b) {
    asm volatile(
        "mma.sync.aligned.m16n8k16.row.col.f32.f16.f16.f32 "
        "{%0,%1,%2,%3},{%4,%5,%6,%7},{%8,%9},{%0,%1,%2,%3};\n"
        : "+f"(d[0]), "+f"(d[1]), "+f"(d[2]), "+f"(d[3])
        : "r"(a[0]), "r"(a[1]), "r"(a[2]), "r"(a[3]), "r"(b[0]), "r"(b[1]));
}

// MODE 0: h = relu(A @ W1[e]^T + b1) -> g_h (fp16)
// MODE 1: out[token] += w * (A @ W2[e]^T + b2)   (atomicAdd; 2 adds/element total)
template <int MODE>
__global__ void __launch_bounds__(512, 1) ffn_gemm(const __half* __restrict__ Abase,
                                                   const __half* __restrict__ Wbase,
                                                   const float* __restrict__ bbase,
                                                   float* __restrict__ out) {
    constexpr int KDIM = (MODE == 0) ? DDIM : HDIM;
    constexpr int NDIM = (MODE == 0) ? HDIM : ODIM;
    constexpr int KT = KDIM / BK;

    const int e = blockIdx.z;
    const int cnt = g_counts[e];
    const int mtile = blockIdx.y;
    if (mtile * BM >= cnt) return;
    const int ntile = blockIdx.x;
    const int off = g_offsets[e];

    extern __shared__ __align__(1024) char smem[];
    const uint32_t sa = smem_u32(smem);            // A stages
    const uint32_t sbB = sa + STAGES * A_STG;      // B stages

    const int tid = threadIdx.x;
    const int lane = tid & 31;
    const int warp = tid >> 5;
    const int wm = warp & 3;   // 4 warp-rows x 64
    const int wn = warp >> 2;  // 4 warp-cols x 32

    const __half* Aexp = Abase + (size_t)(off + mtile * BM) * KDIM;
    const __half* Wexp = Wbase + (size_t)e * NDIM * KDIM + (size_t)(ntile * BN) * KDIM;

    // copy maps: 16B chunks, 8 per 128B row. A: 2048 chunks (4/thread); B: 1024 (2/thread).
    int aRow[4], aC8[4], aSw[4];
#pragma unroll
    for (int i = 0; i < 4; i++) {
        int c = tid + 512 * i;
        aRow[i] = c >> 3;
        aC8[i] = c & 7;
        uint32_t bo = (uint32_t)(aRow[i] * 128 + aC8[i] * 16);
        aSw[i] = (int)(bo ^ ((bo >> 3) & 0x70));
    }
    int bRow[2], bC8[2], bSw[2];
#pragma unroll
    for (int i = 0; i < 2; i++) {
        int c = tid + 512 * i;
        bRow[i] = c >> 3;
        bC8[i] = c & 7;
        uint32_t bo = (uint32_t)(bRow[i] * 128 + bC8[i] * 16);
        bSw[i] = (int)(bo ^ ((bo >> 3) & 0x70));
    }

    auto copy_stage = [&](int kt, int s) {
        const int kb = kt * BK;
#pragma unroll
        for (int i = 0; i < 4; i++)
            cpa16(sa + s * A_STG + aSw[i], Aexp + (size_t)aRow[i] * KDIM + kb + aC8[i] * 8);
#pragma unroll
        for (int i = 0; i < 2; i++)
            cpa16(sbB + s * B_STG + bSw[i], Wexp + (size_t)bRow[i] * KDIM + kb + bC8[i] * 8);
    };

    float acc[4][4][4];
#pragma unroll
    for (int mi = 0; mi < 4; mi++)
#pragma unroll
        for (int ni = 0; ni < 4; ni++)
#pragma unroll
            for (int j = 0; j < 4; j++) acc[mi][ni][j] = 0.f;

    // prologue: fill STAGES-1 = 3 stages
#pragma unroll
    for (int i = 0; i < STAGES - 1; i++) {
        if (i < KT) copy_stage(i, i);
        cpa_commit();
    }

    // fragment addressing (SW128): row&7 is mi/pr-invariant -> XOR factor precomputed
    const int arowL = wm * 64 + (lane & 15);
    const int ahi = lane >> 4;
    const int axor = arowL & 7;
    const int browL = wn * 32 + ((lane >> 4) << 3) + (lane & 7);
    const int bhi = (lane >> 3) & 1;
    const int bxor = lane & 7;

    for (int kt = 0; kt < KT; kt++) {
        const int buf = kt & (STAGES - 1);
        cpa_wait2();
        __syncthreads();
        const uint32_t aBuf = sa + buf * A_STG;
        const uint32_t bBuf = sbB + buf * B_STG;
#pragma unroll
        for (int kk = 0; kk < 4; kk++) {
            const int ac = ((kk * 2 + ahi) ^ axor) << 4;
            const int bc = ((kk * 2 + bhi) ^ bxor) << 4;
            uint32_t af[4][4], bf[4][2];
#pragma unroll
            for (int mi = 0; mi < 4; mi++)
                ldsm4(af[mi][0], af[mi][1], af[mi][2], af[mi][3],
                      aBuf + (arowL + mi * 16) * 128 + ac);
#pragma unroll
            for (int pr = 0; pr < 2; pr++)
                ldsm4(bf[pr * 2][0], bf[pr * 2][1], bf[pr * 2 + 1][0], bf[pr * 2 + 1][1],
                      bBuf + (browL + pr * 16) * 128 + bc);
#pragma unroll
            for (int mi = 0; mi < 4; mi++)
#pragma unroll
                for (int ni = 0; ni < 4; ni++) mma16816(acc[mi][ni], af[mi], bf[ni]);
        }
        __syncthreads();
        if (kt + STAGES - 1 < KT) copy_stage(kt + STAGES - 1, (kt + STAGES - 1) & (STAGES - 1));
        cpa_commit();
    }

    // ---- epilogue (identical to R7) ----
    const int lrow = lane >> 2;
    const int lcol = (lane & 3) * 2;
#pragma unroll
    for (int mi = 0; mi < 4; mi++) {
#pragma unroll
        for (int hh = 0; hh < 2; hh++) {
            int rloc = wm * 64 + mi * 16 + lrow + hh * 8;
            int gm = mtile * BM + rloc;
            if (gm < cnt) {
                if constexpr (MODE == 0) {
                    __half* hrow = g_h + (size_t)(off + gm) * HDIM;
#pragma unroll
                    for (int ni = 0; ni < 4; ni++) {
                        int col = ntile * BN + wn * 32 + ni * 8 + lcol;
                        float c0 = acc[mi][ni][hh * 2 + 0] + __ldg(&bbase[e * NDIM + col]);
                        float c1 = acc[mi][ni][hh * 2 + 1] + __ldg(&bbase[e * NDIM + col + 1]);
                        __half2 hv = __floats2half2_rn(fmaxf(c0, 0.f), fmaxf(c1, 0.f));
                        *reinterpret_cast<__half2*>(hrow + col) = hv;
                    }
                } else {
                    float w = g_slot_w[off + gm];
                    float* orow = out + (size_t)g_slot_token[off + gm] * ODIM;
#pragma unroll
                    for (int ni = 0; ni < 4; ni++) {
                        int col = ntile * BN + wn * 32 + ni * 8 + lcol;
                        float c0 = acc[mi][ni][hh * 2 + 0] + __ldg(&bbase[e * NDIM + col]);
                        float c1 = acc[mi][ni][hh * 2 + 1] + __ldg(&bbase[e * NDIM + col + 1]);
                        atomicAdd(&orow[col], w * c0);
                        atomicAdd(&orow[col + 1], w * c1);
                    }
                }
            }
        }
    }
}

// ---------------- launch ----------------
extern "C" void kernel_launch(void* const* d_in, const int* in_sizes, int n_in,
                              void* d_out, int out_size) {
    const float* x  = (const float*)d_in[0];
    const float* gW = (const float*)d_in[1];
    const float* gb = (const float*)d_in[2];
    const float* W1 = (const float*)d_in[3];
    const float* b1 = (const float*)d_in[4];
    const float* W2 = (const float*)d_in[5];
    const float* b2 = (const float*)d_in[6];
    float* out = (float*)d_out;

    cudaFuncSetAttribute(ffn_gemm<0>, cudaFuncAttributeMaxDynamicSharedMemorySize, GEMM_SMEM);
    cudaFuncSetAttribute(ffn_gemm<1>, cudaFuncAttributeMaxDynamicSharedMemorySize, GEMM_SMEM);

    __half* wbuf = nullptr; __half* xad = nullptr; __half* hd = nullptr;
    cudaGetSymbolAddress((void**)&wbuf, g_wbuf);
    cudaGetSymbolAddress((void**)&xad, g_xa);
    cudaGetSymbolAddress((void**)&hd, g_h);
    size_t n8w = (size_t)NEXP * HDIM * DDIM / 8;

    zero_init_kernel<<<2048, 256>>>(out, (long long)out_size);
    router_kernel<<<NTOK / 8, 256>>>(x, gW, gb);
    assign_kernel<<<NEXP, 256>>>(out, (long long)out_size - 1);
    gather_x_kernel<<<MAXSLOTS, 256>>>(x);
    convert_w_kernel<<<4096, 256>>>(W1, wbuf, n8w);
    ffn_gemm<0><<<dim3(HDIM / BN, MAXSLOTS / BM, NEXP), 512, GEMM_SMEM>>>(xad, wbuf, b1, nullptr);
    convert_w_kernel<<<4096, 256>>>(W2, wbuf, n8w);
    ffn_gemm<1><<<dim3(ODIM / BN, MAXSLOTS / BM, NEXP), 512, GEMM_SMEM>>>(hd, wbuf, b2, out);
}

// round 17
// speedup vs baseline: 1.2618x; 1.0243x over previous
#include <cuda_runtime.h>
#include <cuda_fp16.h>
#include <cstdint>
#include <math.h>

#define NTOK 8192
#define DDIM 2048
#define HDIM 8192
#define ODIM 2048
#define NEXP 8
#define MAXSLOTS (NTOK * 2)
#define SLOTPAD (MAXSLOTS + 256)

// ---------------- device scratch (static: no allocations allowed) ----------------
__device__ __align__(16) __half g_wbuf[(size_t)NEXP * HDIM * DDIM]; // 268 MB (reused W1->W2)
__device__ __align__(16) __half g_xa[(size_t)SLOTPAD * DDIM];       // gathered x, fp16
__device__ __align__(16) __half g_h [(size_t)SLOTPAD * HDIM];       // hidden acts, fp16
__device__ int    g_slot_token[MAXSLOTS];
__device__ float  g_slot_w[MAXSLOTS];
__device__ int    g_tok_e[NTOK * 2];
__device__ float  g_tok_w[NTOK * 2];
__device__ int    g_counts[NEXP];
__device__ int    g_offsets[NEXP + 1];
__device__ float  g_blockP[NTOK / 8][NEXP];   // per-block gate-prob partial sums
__device__ int    g_blockC[NTOK / 8][NEXP];   // per-block expert partial counts

// ---------------- router + zero-out fused (launch #1) ----------------
// Per-block partials written with plain stores -> no global counter init needed,
// no ordering hazard. assign_kernel reduces them deterministically.
__global__ void router2_kernel(const float* __restrict__ x,
                               const float* __restrict__ gW,
                               const float* __restrict__ gb,
                               float* __restrict__ out, long long nout) {
    {   // fused zero of out (lbIdx element overwritten later by assign_kernel)
        long long i = (long long)blockIdx.x * blockDim.x + threadIdx.x;
        long long stride = (long long)gridDim.x * blockDim.x;
        for (; i < nout; i += stride) out[i] = 0.f;
    }
    __shared__ float sP[NEXP];
    __shared__ int sC[NEXP];
    int tid = threadIdx.x, lane = tid & 31, warp = tid >> 5;
    if (tid < NEXP) { sP[tid] = 0.f; sC[tid] = 0; }
    __syncthreads();

    int n = blockIdx.x * 8 + warp;
    float acc[NEXP];
#pragma unroll
    for (int e = 0; e < NEXP; e++) acc[e] = 0.f;
    const float* xr = x + (size_t)n * DDIM;
    for (int d = lane; d < DDIM; d += 32) {
        float xv = xr[d];
        const float4* g = reinterpret_cast<const float4*>(gW + (size_t)d * NEXP);
        float4 g0 = g[0], g1 = g[1];
        acc[0] += xv * g0.x; acc[1] += xv * g0.y; acc[2] += xv * g0.z; acc[3] += xv * g0.w;
        acc[4] += xv * g1.x; acc[5] += xv * g1.y; acc[6] += xv * g1.z; acc[7] += xv * g1.w;
    }
#pragma unroll
    for (int e = 0; e < NEXP; e++) {
        float v = acc[e];
#pragma unroll
        for (int o = 16; o > 0; o >>= 1) v += __shfl_xor_sync(0xffffffffu, v, o);
        acc[e] = v;
    }
    if (lane == 0) {
        float p[NEXP];
        float m = -1e30f;
#pragma unroll
        for (int e = 0; e < NEXP; e++) { p[e] = acc[e] + gb[e]; m = fmaxf(m, p[e]); }
        float s = 0.f;
#pragma unroll
        for (int e = 0; e < NEXP; e++) { p[e] = expf(p[e] - m); s += p[e]; }
        float inv = 1.f / s;
#pragma unroll
        for (int e = 0; e < NEXP; e++) { p[e] *= inv; atomicAdd(&sP[e], p[e]); }
        int i0 = 0;
#pragma unroll
        for (int e = 1; e < NEXP; e++) if (p[e] > p[i0]) i0 = e;
        int i1 = (i0 == 0) ? 1 : 0;
#pragma unroll
        for (int e = 0; e < NEXP; e++) if (e != i0 && p[e] > p[i1]) i1 = e;
        float g0 = p[i0], g1 = p[i1], winv = 1.f / (g0 + g1);
        g_tok_e[2 * n] = i0;  g_tok_e[2 * n + 1] = i1;
        g_tok_w[2 * n] = g0 * winv;  g_tok_w[2 * n + 1] = g1 * winv;
        atomicAdd(&sC[i0], 1); atomicAdd(&sC[i1], 1);
    }
    __syncthreads();
    if (tid < NEXP) {
        g_blockP[blockIdx.x][tid] = sP[tid];
        g_blockC[blockIdx.x][tid] = sC[tid];
    }
}

// ---------------- assign: reduce partials, offsets, lb_loss, scatter (launch #2) ----------
__global__ void assign_kernel(float* __restrict__ out, long long lbIdx) {
    const int e = blockIdx.x;
    const int tid = threadIdx.x;
    __shared__ int svals[256];
    __shared__ int sbase;
    __shared__ int scnt[NEXP];
    if (tid < NEXP) {
        int tot = 0;
        for (int b = 0; b < NTOK / 8; b++) tot += g_blockC[b][tid];
        scnt[tid] = tot;
    }
    __syncthreads();
    if (tid == 0) {
        int off = 0;
        for (int i = 0; i < e; i++) off += scnt[i];
        sbase = off;
        g_offsets[e] = off;
        g_counts[e] = scnt[e];
        if (e == 0) {
            int tot = 0;
#pragma unroll
            for (int i = 0; i < NEXP; i++) tot += scnt[i];
            g_offsets[NEXP] = tot;
            float lb = 0.f;
            for (int i = 0; i < NEXP; i++) {
                float s = 0.f;
                for (int b = 0; b < NTOK / 8; b++) s += g_blockP[b][i];
                float P = s / (float)NTOK;
                lb += P * P;
            }
            out[lbIdx] = lb * (float)NEXP;
        }
    }
    __syncthreads();
    for (int t0 = 0; t0 < NTOK; t0 += 256) {
        int n = t0 + tid;
        int sel = 0; float w = 0.f;
        int e0 = g_tok_e[2 * n], e1 = g_tok_e[2 * n + 1];
        if (e0 == e)      { sel = 1; w = g_tok_w[2 * n]; }
        else if (e1 == e) { sel = 1; w = g_tok_w[2 * n + 1]; }
        svals[tid] = sel;
        __syncthreads();
#pragma unroll
        for (int o = 1; o < 256; o <<= 1) {
            int t = (tid >= o) ? svals[tid - o] : 0;
            __syncthreads();
            svals[tid] += t;
            __syncthreads();
        }
        if (sel) {
            int pos = sbase + svals[tid] - 1;
            g_slot_token[pos] = n;
            g_slot_w[pos] = w;
        }
        int total = svals[255];
        __syncthreads();
        if (tid == 0) sbase += total;
        __syncthreads();
    }
}

// ---------------- gather x + convert W1 fused (launch #3) ----------------
__global__ void gather_convert_kernel(const float* __restrict__ x,
                                      const float* __restrict__ wsrc,
                                      __half* __restrict__ wdst, size_t n8) {
    int slot = blockIdx.x;
    int token = g_slot_token[slot];
    const float* src = x + (size_t)token * DDIM;
    __half* dst = g_xa + (size_t)slot * DDIM;
    int t = threadIdx.x;
#pragma unroll
    for (int i = 0; i < 2; i++) {
        int c = (t + i * 256) * 4;
        float4 v = *reinterpret_cast<const float4*>(src + c);
        __half2 h0 = __floats2half2_rn(v.x, v.y);
        __half2 h1 = __floats2half2_rn(v.z, v.w);
        *reinterpret_cast<uint2*>(dst + c) = make_uint2(*(uint32_t*)&h0, *(uint32_t*)&h1);
    }
    size_t i = (size_t)blockIdx.x * blockDim.x + threadIdx.x;
    size_t stride = (size_t)gridDim.x * blockDim.x;
    for (; i < n8; i += stride) {
        const float4* s = reinterpret_cast<const float4*>(wsrc + i * 8);
        float4 v0 = s[0], v1 = s[1];
        __half2 h0 = __floats2half2_rn(v0.x, v0.y);
        __half2 h1 = __floats2half2_rn(v0.z, v0.w);
        __half2 h2 = __floats2half2_rn(v1.x, v1.y);
        __half2 h3 = __floats2half2_rn(v1.z, v1.w);
        uint2* d = reinterpret_cast<uint2*>(wdst + i * 8);
        d[0] = make_uint2(*(uint32_t*)&h0, *(uint32_t*)&h1);
        d[1] = make_uint2(*(uint32_t*)&h2, *(uint32_t*)&h3);
    }
}

// ---------------- plain W convert (for W2, launch #5) ----------------
__global__ void convert_w_kernel(const float* __restrict__ src, __half* __restrict__ dst,
                                 size_t n8) {
    size_t i = (size_t)blockIdx.x * blockDim.x + threadIdx.x;
    size_t stride = (size_t)gridDim.x * blockDim.x;
    for (; i < n8; i += stride) {
        const float4* s = reinterpret_cast<const float4*>(src + i * 8);
        float4 v0 = s[0], v1 = s[1];
        __half2 h0 = __floats2half2_rn(v0.x, v0.y);
        __half2 h1 = __floats2half2_rn(v0.z, v0.w);
        __half2 h2 = __floats2half2_rn(v1.x, v1.y);
        __half2 h3 = __floats2half2_rn(v1.z, v1.w);
        uint2* d = reinterpret_cast<uint2*>(dst + i * 8);
        d[0] = make_uint2(*(uint32_t*)&h0, *(uint32_t*)&h1);
        d[1] = make_uint2(*(uint32_t*)&h2, *(uint32_t*)&h3);
    }
}

// ------- HMMA GEMM: BM=256 BN=128 BK=64 (SW128 128B rows), 512 thr, 4-stage cp.async -------
#define BM 256
#define BN 128
#define BK 64
#define STAGES 4
#define A_STG (BM * 128)                       // 32768 B
#define B_STG (BN * 128)                       // 16384 B
#define GEMM_SMEM (STAGES * (A_STG + B_STG))   // 196608 B

__device__ __forceinline__ uint32_t smem_u32(const void* p) {
    uint32_t a;
    asm("{ .reg .u64 t; cvta.to.shared.u64 t, %1; cvt.u32.u64 %0, t; }" : "=r"(a) : "l"(p));
    return a;
}
__device__ __forceinline__ void cpa16(uint32_t dst, const void* src) {
    asm volatile("cp.async.cg.shared.global [%0], [%1], 16;" :: "r"(dst), "l"(src));
}
__device__ __forceinline__ void cpa_commit() {
    asm volatile("cp.async.commit_group;" ::: "memory");
}
__device__ __forceinline__ void cpa_wait2() {
    asm volatile("cp.async.wait_group 2;" ::: "memory");
}
__device__ __forceinline__ void ldsm4(uint32_t& r0, uint32_t& r1, uint32_t& r2, uint32_t& r3,
                                      uint32_t addr) {
    asm volatile("ldmatrix.sync.aligned.m8n8.x4.shared.b16 {%0,%1,%2,%3}, [%4];\n"
                 : "=r"(r0), "=r"(r1), "=r"(r2), "=r"(r3) : "r"(addr));
}
__device__ __forceinline__ void mma16816(float* d, const uint32_t* a, const uint32_t* b) {
    asm volatile(
        "mma.sync.aligned.m16n8k16.row.col.f32.f16.f16.f32 "
        "{%0,%1,%2,%3},{%4,%5,%6,%7},{%8,%9},{%0,%1,%2,%3};\n"
        : "+f"(d[0]), "+f"(d[1]), "+f"(d[2]), "+f"(d[3])
        : "r"(a[0]), "r"(a[1]), "r"(a[2]), "r"(a[3]), "r"(b[0]), "r"(b[1]));
}

// MODE 0: h = relu(A @ W1[e]^T + b1) -> g_h (fp16)
// MODE 1: out[token] += w * (A @ W2[e]^T + b2)   (atomicAdd; 2 adds/element total)
template <int MODE>
__global__ void __launch_bounds__(512, 1) ffn_gemm(const __half* __restrict__ Abase,
                                                   const __half* __restrict__ Wbase,
                                                   const float* __restrict__ bbase,
                                                   float* __restrict__ out) {
    constexpr int KDIM = (MODE == 0) ? DDIM : HDIM;
    constexpr int NDIM = (MODE == 0) ? HDIM : ODIM;
    constexpr int KT = KDIM / BK;

    const int e = blockIdx.z;
    const int cnt = g_counts[e];
    const int mtile = blockIdx.y;
    if (mtile * BM >= cnt) return;
    const int ntile = blockIdx.x;
    const int off = g_offsets[e];

    extern __shared__ __align__(1024) char smem[];
    const uint32_t sa = smem_u32(smem);
    const uint32_t sbB = sa + STAGES * A_STG;

    const int tid = threadIdx.x;
    const int lane = tid & 31;
    const int warp = tid >> 5;
    const int wm = warp & 3;
    const int wn = warp >> 2;

    const __half* Aexp = Abase + (size_t)(off + mtile * BM) * KDIM;
    const __half* Wexp = Wbase + (size_t)e * NDIM * KDIM + (size_t)(ntile * BN) * KDIM;

    int aRow[4], aC8[4], aSw[4];
#pragma unroll
    for (int i = 0; i < 4; i++) {
        int c = tid + 512 * i;
        aRow[i] = c >> 3;
        aC8[i] = c & 7;
        uint32_t bo = (uint32_t)(aRow[i] * 128 + aC8[i] * 16);
        aSw[i] = (int)(bo ^ ((bo >> 3) & 0x70));
    }
    int bRow[2], bC8[2], bSw[2];
#pragma unroll
    for (int i = 0; i < 2; i++) {
        int c = tid + 512 * i;
        bRow[i] = c >> 3;
        bC8[i] = c & 7;
        uint32_t bo = (uint32_t)(bRow[i] * 128 + bC8[i] * 16);
        bSw[i] = (int)(bo ^ ((bo >> 3) & 0x70));
    }

    auto copy_stage = [&](int kt, int s) {
        const int kb = kt * BK;
#pragma unroll
        for (int i = 0; i < 4; i++)
            cpa16(sa + s * A_STG + aSw[i], Aexp + (size_t)aRow[i] * KDIM + kb + aC8[i] * 8);
#pragma unroll
        for (int i = 0; i < 2; i++)
            cpa16(sbB + s * B_STG + bSw[i], Wexp + (size_t)bRow[i] * KDIM + kb + bC8[i] * 8);
    };

    float acc[4][4][4];
#pragma unroll
    for (int mi = 0; mi < 4; mi++)
#pragma unroll
        for (int ni = 0; ni < 4; ni++)
#pragma unroll
            for (int j = 0; j < 4; j++) acc[mi][ni][j] = 0.f;

#pragma unroll
    for (int i = 0; i < STAGES - 1; i++) {
        if (i < KT) copy_stage(i, i);
        cpa_commit();
    }

    const int arowL = wm * 64 + (lane & 15);
    const int ahi = lane >> 4;
    const int axor = arowL & 7;
    const int browL = wn * 32 + ((lane >> 4) << 3) + (lane & 7);
    const int bhi = (lane >> 3) & 1;
    const int bxor = lane & 7;

    for (int kt = 0; kt < KT; kt++) {
        const int buf = kt & (STAGES - 1);
        cpa_wait2();
        __syncthreads();   // single barrier: publishes stage buf AND proves the stage
                           // refilled below was fully consumed at iter kt-1
        const uint32_t aBuf = sa + buf * A_STG;
        const uint32_t bBuf = sbB + buf * B_STG;
#pragma unroll
        for (int kk = 0; kk < 4; kk++) {
            const int ac = ((kk * 2 + ahi) ^ axor) << 4;
            const int bc = ((kk * 2 + bhi) ^ bxor) << 4;
            uint32_t af[4][4], bf[4][2];
#pragma unroll
            for (int mi = 0; mi < 4; mi++)
                ldsm4(af[mi][0], af[mi][1], af[mi][2], af[mi][3],
                      aBuf + (arowL + mi * 16) * 128 + ac);
#pragma unroll
            for (int pr = 0; pr < 2; pr++)
                ldsm4(bf[pr * 2][0], bf[pr * 2][1], bf[pr * 2 + 1][0], bf[pr * 2 + 1][1],
                      bBuf + (browL + pr * 16) * 128 + bc);
#pragma unroll
            for (int mi = 0; mi < 4; mi++)
#pragma unroll
                for (int ni = 0; ni < 4; ni++) mma16816(acc[mi][ni], af[mi], bf[ni]);
        }
        if (kt + STAGES - 1 < KT) copy_stage(kt + STAGES - 1, (kt + STAGES - 1) & (STAGES - 1));
        cpa_commit();
    }

    const int lrow = lane >> 2;
    const int lcol = (lane & 3) * 2;
#pragma unroll
    for (int mi = 0; mi < 4; mi++) {
#pragma unroll
        for (int hh = 0; hh < 2; hh++) {
            int rloc = wm * 64 + mi * 16 + lrow + hh * 8;
            int gm = mtile * BM + rloc;
            if (gm < cnt) {
                if constexpr (MODE == 0) {
                    __half* hrow = g_h + (size_t)(off + gm) * HDIM;
#pragma unroll
                    for (int ni = 0; ni < 4; ni++) {
                        int col = ntile * BN + wn * 32 + ni * 8 + lcol;
                        float c0 = acc[mi][ni][hh * 2 + 0] + __ldg(&bbase[e * NDIM + col]);
                        float c1 = acc[mi][ni][hh * 2 + 1] + __ldg(&bbase[e * NDIM + col + 1]);
                        __half2 hv = __floats2half2_rn(fmaxf(c0, 0.f), fmaxf(c1, 0.f));
                        *reinterpret_cast<__half2*>(hrow + col) = hv;
                    }
                } else {
                    float w = g_slot_w[off + gm];
                    float* orow = out + (size_t)g_slot_token[off + gm] * ODIM;
#pragma unroll
                    for (int ni = 0; ni < 4; ni++) {
                        int col = ntile * BN + wn * 32 + ni * 8 + lcol;
                        float c0 = acc[mi][ni][hh * 2 + 0] + __ldg(&bbase[e * NDIM + col]);
                        float c1 = acc[mi][ni][hh * 2 + 1] + __ldg(&bbase[e * NDIM + col + 1]);
                        atomicAdd(&orow[col], w * c0);
                        atomicAdd(&orow[col + 1], w * c1);
                    }
                }
            }
        }
    }
}

// ---------------- launch ----------------
extern "C" void kernel_launch(void* const* d_in, const int* in_sizes, int n_in,
                              void* d_out, int out_size) {
    const float* x  = (const float*)d_in[0];
    const float* gW = (const float*)d_in[1];
    const float* gb = (const float*)d_in[2];
    const float* W1 = (const float*)d_in[3];
    const float* b1 = (const float*)d_in[4];
    const float* W2 = (const float*)d_in[5];
    const float* b2 = (const float*)d_in[6];
    float* out = (float*)d_out;

    cudaFuncSetAttribute(ffn_gemm<0>, cudaFuncAttributeMaxDynamicSharedMemorySize, GEMM_SMEM);
    cudaFuncSetAttribute(ffn_gemm<1>, cudaFuncAttributeMaxDynamicSharedMemorySize, GEMM_SMEM);

    __half* wbuf = nullptr; __half* xad = nullptr; __half* hd = nullptr;
    cudaGetSymbolAddress((void**)&wbuf, g_wbuf);
    cudaGetSymbolAddress((void**)&xad, g_xa);
    cudaGetSymbolAddress((void**)&hd, g_h);
    size_t n8w = (size_t)NEXP * HDIM * DDIM / 8;

    // #1 router (+ zero out, per-block partial counts/probs — no init races)
    router2_kernel<<<NTOK / 8, 256>>>(x, gW, gb, out, (long long)out_size);
    // #2 assign (reduces partials, writes offsets/counts + lb_loss, scatters slots)
    assign_kernel<<<NEXP, 256>>>(out, (long long)out_size - 1);
    // #3 gather x + convert W1 (fused)
    gather_convert_kernel<<<MAXSLOTS, 256>>>(x, W1, wbuf, n8w);
    // #4 GEMM1  <-- ncu captures my 4th launch
    ffn_gemm<0><<<dim3(HDIM / BN, MAXSLOTS / BM, NEXP), 512, GEMM_SMEM>>>(xad, wbuf, b1, nullptr);
    // #5 convert W2
    convert_w_kernel<<<4096, 256>>>(W2, wbuf, n8w);
    // #6 GEMM2
    ffn_gemm<1><<<dim3(ODIM / BN, MAXSLOTS / BM, NEXP), 512, GEMM_SMEM>>>(hd, wbuf, b2, out);
}